// round 8
// baseline (speedup 1.0000x reference)
#include <cuda_runtime.h>

// NonMaximaSuppression2d: x (8,32,512,512) fp32.
// m = max over 8 neighbors (replicate pad), floored at 0 (zeroed center tap).
// out = x * (x > m).
// R7: RPT 4->2. ncu curve {32,16,8,4}->{86.0,87.2,79.4,78.0}us. At RPT=2 the
// fully-unrolled body has 4 independent row loads -> ptxas front-batches them
// (MLP_p1~4). Halo 2.0x but L2-resident (adjacent CTAs, tiny reuse distance).
// __launch_bounds__(128,16) pins <=32 regs / 16 CTAs/SM.

#define HH 512
#define WW 512
#define RPT 2           // rows per thread strip
#define TPB 128         // threads per block = WW/4 float4 groups

struct RowRegs {
    float4 v;   // 4 center values
    float  l;   // value at col-1 (replicated at left edge)
    float  r;   // value at col+4 (replicated at right edge)
};

__device__ __forceinline__ void load_row(const float* __restrict__ img,
                                         int y, int c, RowRegs& rr) {
    int yc = min(max(y, 0), HH - 1);
    const float* p = img + (size_t)yc * WW + c;
    rr.v = *reinterpret_cast<const float4*>(p);
    // edge scalars hit the same 128B lines as neighbor lanes' vectors -> L1
    rr.l = (c > 0)      ? __ldg(p - 1) : rr.v.x;
    rr.r = (c + 4 < WW) ? __ldg(p + 4) : rr.v.w;
}

// max of 3 horizontally adjacent values per lane (rows above/below)
__device__ __forceinline__ float4 hmax3(const RowRegs& rr) {
    float4 h;
    h.x = fmaxf(fmaxf(rr.l,   rr.v.x), rr.v.y);
    h.y = fmaxf(fmaxf(rr.v.x, rr.v.y), rr.v.z);
    h.z = fmaxf(fmaxf(rr.v.y, rr.v.z), rr.v.w);
    h.w = fmaxf(fmaxf(rr.v.z, rr.v.w), rr.r);
    return h;
}

// max of the 2 horizontal neighbors (center excluded; for the center row)
__device__ __forceinline__ float4 hmax2(const RowRegs& rr) {
    float4 h;
    h.x = fmaxf(rr.l,   rr.v.y);
    h.y = fmaxf(rr.v.x, rr.v.z);
    h.z = fmaxf(rr.v.y, rr.v.w);
    h.w = fmaxf(rr.v.z, rr.r);
    return h;
}

__global__ __launch_bounds__(TPB, 16)
void nms2d_kernel(const float* __restrict__ x, float* __restrict__ out) {
    const int tiles_per_img = HH / RPT;             // 256
    const int img  = blockIdx.x / tiles_per_img;
    const int tile = blockIdx.x % tiles_per_img;

    const float* in = x   + (size_t)img * HH * WW;
    float*       o  = out + (size_t)img * HH * WW;

    const int c  = threadIdx.x * 4;                 // 0..508
    const int y0 = tile * RPT;

    RowRegs prev, cur, next;
    load_row(in, y0 - 1, c, prev);
    load_row(in, y0,     c, cur);

    float* op = o + (size_t)y0 * WW + c;

    #pragma unroll
    for (int i = 0; i < RPT; i++) {
        load_row(in, y0 + i + 1, c, next);

        float4 mp = hmax3(prev);
        float4 mc = hmax2(cur);
        float4 mn = hmax3(next);

        // fold the zeroed-center-tap floor (reference inits max at 0)
        float4 m;
        m.x = fmaxf(fmaxf(fmaxf(mp.x, mc.x), mn.x), 0.0f);
        m.y = fmaxf(fmaxf(fmaxf(mp.y, mc.y), mn.y), 0.0f);
        m.z = fmaxf(fmaxf(fmaxf(mp.z, mc.z), mn.z), 0.0f);
        m.w = fmaxf(fmaxf(fmaxf(mp.w, mc.w), mn.w), 0.0f);

        float4 xc = cur.v;
        float4 r;
        r.x = (xc.x > m.x) ? xc.x : 0.0f;
        r.y = (xc.y > m.y) ? xc.y : 0.0f;
        r.z = (xc.z > m.z) ? xc.z : 0.0f;
        r.w = (xc.w > m.w) ? xc.w : 0.0f;

        // streaming store: output never re-read; keep L2 for input halos
        __stcs(reinterpret_cast<float4*>(op), r);
        op += WW;

        prev = cur;
        cur  = next;
    }
}

extern "C" void kernel_launch(void* const* d_in, const int* in_sizes, int n_in,
                              void* d_out, int out_size) {
    const float* x = (const float*)d_in[0];
    float* out = (float*)d_out;

    const int n_img = in_sizes[0] / (HH * WW);      // B*C = 256
    const int blocks = n_img * (HH / RPT);          // 65536

    nms2d_kernel<<<blocks, TPB>>>(x, out);
}

// round 9
// speedup vs baseline: 1.0706x; 1.0706x over previous
#include <cuda_runtime.h>

// NonMaximaSuppression2d: x (8,32,512,512) fp32.
// m = max over 8 neighbors (replicate pad), floored at 0 (zeroed center tap).
// out = x * (x > m).
// R8: RPT curve mapped {32:86.0, 16:87.2, 8:79.4, 4:78.0, 2:84.9}us ncu ->
// RPT=4 optimum. Single change vs R6(RPT4): drop __stcs, plain write-back
// stores (R2 plain=5982GB/s vs R3 stcs=5832GB/s suggests .cs hurts LTS
// write-coalescing; L2 only 43% utilized so "save L2 for halo" is moot).

#define HH 512
#define WW 512
#define RPT 4           // rows per thread strip
#define TPB 128         // threads per block = WW/4 float4 groups

struct RowRegs {
    float4 v;   // 4 center values
    float  l;   // value at col-1 (replicated at left edge)
    float  r;   // value at col+4 (replicated at right edge)
};

__device__ __forceinline__ void load_row(const float* __restrict__ img,
                                         int y, int c, RowRegs& rr) {
    int yc = min(max(y, 0), HH - 1);
    const float* p = img + (size_t)yc * WW + c;
    rr.v = *reinterpret_cast<const float4*>(p);
    // edge scalars hit the same 128B lines as neighbor lanes' vectors -> L1
    rr.l = (c > 0)      ? __ldg(p - 1) : rr.v.x;
    rr.r = (c + 4 < WW) ? __ldg(p + 4) : rr.v.w;
}

// max of 3 horizontally adjacent values per lane (rows above/below)
__device__ __forceinline__ float4 hmax3(const RowRegs& rr) {
    float4 h;
    h.x = fmaxf(fmaxf(rr.l,   rr.v.x), rr.v.y);
    h.y = fmaxf(fmaxf(rr.v.x, rr.v.y), rr.v.z);
    h.z = fmaxf(fmaxf(rr.v.y, rr.v.z), rr.v.w);
    h.w = fmaxf(fmaxf(rr.v.z, rr.v.w), rr.r);
    return h;
}

// max of the 2 horizontal neighbors (center excluded; for the center row)
__device__ __forceinline__ float4 hmax2(const RowRegs& rr) {
    float4 h;
    h.x = fmaxf(rr.l,   rr.v.y);
    h.y = fmaxf(rr.v.x, rr.v.z);
    h.z = fmaxf(rr.v.y, rr.v.w);
    h.w = fmaxf(rr.v.z, rr.r);
    return h;
}

__global__ __launch_bounds__(TPB, 16)
void nms2d_kernel(const float* __restrict__ x, float* __restrict__ out) {
    const int tiles_per_img = HH / RPT;             // 128
    const int img  = blockIdx.x / tiles_per_img;
    const int tile = blockIdx.x % tiles_per_img;

    const float* in = x   + (size_t)img * HH * WW;
    float*       o  = out + (size_t)img * HH * WW;

    const int c  = threadIdx.x * 4;                 // 0..508
    const int y0 = tile * RPT;

    RowRegs prev, cur, next;
    load_row(in, y0 - 1, c, prev);
    load_row(in, y0,     c, cur);

    float* op = o + (size_t)y0 * WW + c;

    #pragma unroll
    for (int i = 0; i < RPT; i++) {
        load_row(in, y0 + i + 1, c, next);

        float4 mp = hmax3(prev);
        float4 mc = hmax2(cur);
        float4 mn = hmax3(next);

        // fold the zeroed-center-tap floor (reference inits max at 0)
        float4 m;
        m.x = fmaxf(fmaxf(fmaxf(mp.x, mc.x), mn.x), 0.0f);
        m.y = fmaxf(fmaxf(fmaxf(mp.y, mc.y), mn.y), 0.0f);
        m.z = fmaxf(fmaxf(fmaxf(mp.z, mc.z), mn.z), 0.0f);
        m.w = fmaxf(fmaxf(fmaxf(mp.w, mc.w), mn.w), 0.0f);

        float4 xc = cur.v;
        float4 r;
        r.x = (xc.x > m.x) ? xc.x : 0.0f;
        r.y = (xc.y > m.y) ? xc.y : 0.0f;
        r.z = (xc.z > m.z) ? xc.z : 0.0f;
        r.w = (xc.w > m.w) ? xc.w : 0.0f;

        // plain write-back store (A/B vs __stcs)
        *reinterpret_cast<float4*>(op) = r;
        op += WW;

        prev = cur;
        cur  = next;
    }
}

extern "C" void kernel_launch(void* const* d_in, const int* in_sizes, int n_in,
                              void* d_out, int out_size) {
    const float* x = (const float*)d_in[0];
    float* out = (float*)d_out;

    const int n_img = in_sizes[0] / (HH * WW);      // B*C = 256
    const int blocks = n_img * (HH / RPT);          // 32768

    nms2d_kernel<<<blocks, TPB>>>(x, out);
}

// round 10
// speedup vs baseline: 1.0919x; 1.0199x over previous
#include <cuda_runtime.h>

// NonMaximaSuppression2d: x (8,32,512,512) fp32.
// m = max over 8 neighbors (replicate pad), floored at 0 (zeroed center tap).
// out = x * (x > m).
// R9: RPT=4 with ALL 6 window rows loaded up-front (6 independent LDG.128,
// MLP_p1~6) before any compute. launch_bounds(128,12) relaxes the reg cap to
// ~40 (occ 75%): outstanding loads/SM 12*4*6=288 vs 16*4*2=128 previously.
// Store policy: plain write-back (R8 A/B showed stcs neutral).

#define HH 512
#define WW 512
#define RPT 4           // rows per output strip
#define NROWS (RPT + 2) // 6 rows in the window
#define TPB 128         // threads per block = WW/4 float4 groups

struct RowRegs {
    float4 v;   // 4 center values
    float  l;   // value at col-1 (replicated at left edge)
    float  r;   // value at col+4 (replicated at right edge)
};

__device__ __forceinline__ void load_row(const float* __restrict__ img,
                                         int y, int c, RowRegs& rr) {
    int yc = min(max(y, 0), HH - 1);
    const float* p = img + (size_t)yc * WW + c;
    rr.v = *reinterpret_cast<const float4*>(p);
    // edge scalars hit the same 128B lines as neighbor lanes' vectors -> L1
    rr.l = (c > 0)      ? __ldg(p - 1) : rr.v.x;
    rr.r = (c + 4 < WW) ? __ldg(p + 4) : rr.v.w;
}

// max of 3 horizontally adjacent values per lane (rows above/below)
__device__ __forceinline__ float4 hmax3(const RowRegs& rr) {
    float4 h;
    h.x = fmaxf(fmaxf(rr.l,   rr.v.x), rr.v.y);
    h.y = fmaxf(fmaxf(rr.v.x, rr.v.y), rr.v.z);
    h.z = fmaxf(fmaxf(rr.v.y, rr.v.z), rr.v.w);
    h.w = fmaxf(fmaxf(rr.v.z, rr.v.w), rr.r);
    return h;
}

// max of the 2 horizontal neighbors (center excluded; for the center row)
__device__ __forceinline__ float4 hmax2(const RowRegs& rr) {
    float4 h;
    h.x = fmaxf(rr.l,   rr.v.y);
    h.y = fmaxf(rr.v.x, rr.v.z);
    h.z = fmaxf(rr.v.y, rr.v.w);
    h.w = fmaxf(rr.v.z, rr.r);
    return h;
}

__global__ __launch_bounds__(TPB, 12)
void nms2d_kernel(const float* __restrict__ x, float* __restrict__ out) {
    const int tiles_per_img = HH / RPT;             // 128
    const int img  = blockIdx.x / tiles_per_img;
    const int tile = blockIdx.x % tiles_per_img;

    const float* in = x   + (size_t)img * HH * WW;
    float*       o  = out + (size_t)img * HH * WW;

    const int c  = threadIdx.x * 4;                 // 0..508
    const int y0 = tile * RPT;

    // front-batch the entire 6-row window: 6 independent LDG.128
    RowRegs w[NROWS];
    #pragma unroll
    for (int k = 0; k < NROWS; k++)
        load_row(in, y0 - 1 + k, c, w[k]);

    float* op = o + (size_t)y0 * WW + c;

    #pragma unroll
    for (int i = 0; i < RPT; i++) {
        float4 mp = hmax3(w[i]);
        float4 mc = hmax2(w[i + 1]);
        float4 mn = hmax3(w[i + 2]);

        // fold the zeroed-center-tap floor (reference inits max at 0)
        float4 m;
        m.x = fmaxf(fmaxf(fmaxf(mp.x, mc.x), mn.x), 0.0f);
        m.y = fmaxf(fmaxf(fmaxf(mp.y, mc.y), mn.y), 0.0f);
        m.z = fmaxf(fmaxf(fmaxf(mp.z, mc.z), mn.z), 0.0f);
        m.w = fmaxf(fmaxf(fmaxf(mp.w, mc.w), mn.w), 0.0f);

        float4 xc = w[i + 1].v;
        float4 r;
        r.x = (xc.x > m.x) ? xc.x : 0.0f;
        r.y = (xc.y > m.y) ? xc.y : 0.0f;
        r.z = (xc.z > m.z) ? xc.z : 0.0f;
        r.w = (xc.w > m.w) ? xc.w : 0.0f;

        *reinterpret_cast<float4*>(op) = r;
        op += WW;
    }
}

extern "C" void kernel_launch(void* const* d_in, const int* in_sizes, int n_in,
                              void* d_out, int out_size) {
    const float* x = (const float*)d_in[0];
    float* out = (float*)d_out;

    const int n_img = in_sizes[0] / (HH * WW);      // B*C = 256
    const int blocks = n_img * (HH / RPT);          // 32768

    nms2d_kernel<<<blocks, TPB>>>(x, out);
}